// round 9
// baseline (speedup 1.0000x reference)
#include <cuda_runtime.h>
#include <cstdint>

// score[e] = dot(h[src[e]], h[dst[e]]), D_FEAT = 128 (fp32), one warp per edge.
// NOTE: edge_index is int32 on device (JAX downcasts int64 -> int32 without x64 mode).
// h (51.2 MB) fits in GB300's ~126 MB L2 -> gathers are L2-bound.
// Each lane loads one float4 from each of the two rows (32 lanes * 16B = 512B row),
// 4 FMAs, butterfly reduction, lane 0 stores the scalar.

static constexpr int D_FEAT = 128;

__global__ void __launch_bounds__(256)
edge_dot_kernel(const float* __restrict__ h,
                const int* __restrict__ src,
                const int* __restrict__ dst,
                float* __restrict__ out,
                int n_edges)
{
    const int warp_id = (int)((blockIdx.x * (unsigned)blockDim.x + threadIdx.x) >> 5);
    const int lane = threadIdx.x & 31;
    if (warp_id >= n_edges) return;

    // All lanes load the same 4B index -> single-sector broadcast, cheap.
    const int s = __ldg(src + warp_id);
    const int d = __ldg(dst + warp_id);

    const float4* __restrict__ hs =
        reinterpret_cast<const float4*>(h + (long long)s * D_FEAT) + lane;
    const float4* __restrict__ hd =
        reinterpret_cast<const float4*>(h + (long long)d * D_FEAT) + lane;

    // Two independent 16B loads -> MLP=2 per lane, 8 L2 lines in flight per warp.
    const float4 a = __ldg(hs);
    const float4 b = __ldg(hd);

    float sum = a.x * b.x + a.y * b.y + a.z * b.z + a.w * b.w;

    #pragma unroll
    for (int off = 16; off > 0; off >>= 1)
        sum += __shfl_xor_sync(0xffffffffu, sum, off);

    if (lane == 0)
        out[warp_id] = sum;
}

extern "C" void kernel_launch(void* const* d_in, const int* in_sizes, int n_in,
                              void* d_out, int out_size)
{
    const float* h = (const float*)d_in[0];          // [N_NODES, 128] fp32
    const int* edge_index = (const int*)d_in[1];     // [2, E] int32 (JAX default)

    const int n_edges = in_sizes[1] / 2;             // E
    const int* src = edge_index;                     // row 0
    const int* dst = edge_index + n_edges;           // row 1

    float* out = (float*)d_out;                      // [E, 1] fp32

    const int threads = 256;                         // 8 warps/block -> 8 edges/block
    const int edges_per_block = threads / 32;
    const int blocks = (n_edges + edges_per_block - 1) / edges_per_block;

    edge_dot_kernel<<<blocks, threads>>>(h, src, dst, out, n_edges);
}

// round 10
// speedup vs baseline: 1.7975x; 1.7975x over previous
#include <cuda_runtime.h>
#include <cstdint>

// score[e] = dot(h[src[e]], h[dst[e]]), D_FEAT = 128 (fp32).
// R9 finding: kernel is LATENCY-bound (L2=36%, L1=48%, DRAM=5%, issue=32%) —
// nothing saturated. Fix: 8 edges per warp, all 16 row-gathers issued
// back-to-back (MLP per warp slot 2 -> 16) before any consumption.
// Indices fetched lane-parallel (1 LDG), outputs stored as two float4.

static constexpr int D_FEAT = 128;
static constexpr int EPW = 8;          // edges per warp
static constexpr int WARPS_PER_BLOCK = 8;

__global__ void __launch_bounds__(256)
edge_dot8_kernel(const float* __restrict__ h,
                 const int* __restrict__ src,
                 const int* __restrict__ dst,
                 float* __restrict__ out,
                 int n_edges)
{
    const int warp = (int)((blockIdx.x * (unsigned)blockDim.x + threadIdx.x) >> 5);
    const int lane = threadIdx.x & 31;
    const int e0 = warp * EPW;
    if (e0 >= n_edges) return;

    if (e0 + EPW <= n_edges) {
        // ---- fast path: full batch of 8 edges ----
        // Lane-parallel index fetch: lanes 0-7 read src[e0..e0+7],
        // lanes 8-15 read dst[e0..e0+7]. One LDG, 1-2 sectors.
        int v = 0;
        if (lane < 16) {
            const int* p = (lane < 8) ? (src + e0 + lane) : (dst + e0 + (lane - 8));
            v = __ldg(p);
        }
        int s[EPW], d[EPW];
        #pragma unroll
        for (int i = 0; i < EPW; i++) {
            s[i] = __shfl_sync(0xffffffffu, v, i);
            d[i] = __shfl_sync(0xffffffffu, v, 8 + i);
        }

        // Issue all 16 gathers before consuming anything -> 16 outstanding
        // LDG.128 per lane slot, 64 L2 lines in flight per warp.
        float4 a[EPW], b[EPW];
        #pragma unroll
        for (int i = 0; i < EPW; i++)
            a[i] = __ldg(reinterpret_cast<const float4*>(
                       h + (size_t)s[i] * D_FEAT) + lane);
        #pragma unroll
        for (int i = 0; i < EPW; i++)
            b[i] = __ldg(reinterpret_cast<const float4*>(
                       h + (size_t)d[i] * D_FEAT) + lane);

        float sum[EPW];
        #pragma unroll
        for (int i = 0; i < EPW; i++)
            sum[i] = a[i].x * b[i].x + a[i].y * b[i].y
                   + a[i].z * b[i].z + a[i].w * b[i].w;

        // 8 independent butterfly reductions (pipelined shuffles).
        #pragma unroll
        for (int off = 16; off > 0; off >>= 1) {
            #pragma unroll
            for (int i = 0; i < EPW; i++)
                sum[i] += __shfl_xor_sync(0xffffffffu, sum[i], off);
        }

        // All lanes hold the totals; lanes 0 and 1 each store one float4.
        if (lane < 2) {
            float4 o = (lane == 0)
                ? make_float4(sum[0], sum[1], sum[2], sum[3])
                : make_float4(sum[4], sum[5], sum[6], sum[7]);
            *reinterpret_cast<float4*>(out + e0 + 4 * lane) = o;
        }
    } else {
        // ---- tail: scalar per-edge path ----
        for (int e = e0; e < n_edges; e++) {
            const int s = __ldg(src + e);
            const int d = __ldg(dst + e);
            const float4 a = __ldg(reinterpret_cast<const float4*>(
                                 h + (size_t)s * D_FEAT) + lane);
            const float4 b = __ldg(reinterpret_cast<const float4*>(
                                 h + (size_t)d * D_FEAT) + lane);
            float sum = a.x * b.x + a.y * b.y + a.z * b.z + a.w * b.w;
            #pragma unroll
            for (int off = 16; off > 0; off >>= 1)
                sum += __shfl_xor_sync(0xffffffffu, sum, off);
            if (lane == 0) out[e] = sum;
        }
    }
}

extern "C" void kernel_launch(void* const* d_in, const int* in_sizes, int n_in,
                              void* d_out, int out_size)
{
    const float* h = (const float*)d_in[0];          // [N_NODES, 128] fp32
    const int* edge_index = (const int*)d_in[1];     // [2, E] int32

    const int n_edges = in_sizes[1] / 2;
    const int* src = edge_index;                     // row 0
    const int* dst = edge_index + n_edges;           // row 1

    float* out = (float*)d_out;                      // [E, 1] fp32

    const int threads = 32 * WARPS_PER_BLOCK;        // 256
    const int edges_per_block = WARPS_PER_BLOCK * EPW;  // 64
    const int blocks = (n_edges + edges_per_block - 1) / edges_per_block;

    edge_dot8_kernel<<<blocks, threads>>>(h, src, dst, out, n_edges);
}